// round 13
// baseline (speedup 1.0000x reference)
#include <cuda_runtime.h>

#define DIMS 2048
#define SEQ  4096
#define SENT 2.0f   // sentinel: tanh output is in (-1,1), h0 = 0 -> never 2.0

#define NCTA_SCAN 128
#define NCTA_GEMM 16
#define NCTA_ALL  (NCTA_SCAN + NCTA_GEMM)   // 144 <= 148 SMs -> one wave
#define RPC  16
#define THREADS 256
#define TBLK 32                              // timesteps per producer block
#define NBLK (SEQ / TBLK)                    // 128

// ---------------- scratch (static device globals; no allocation) ------------
__device__ float g_A[SEQ * DIMS];                         // A = X @ W_hi^T + b
__device__ __align__(16) float g_hist[(SEQ + 1) * DIMS];  // write-once h history
__device__ int   g_blkcnt[NBLK];                          // per-block arrivals
__device__ int   g_Aprog;                                 // prefix of done blocks

// ---------------- small asm helpers -----------------------------------------
__device__ __forceinline__ float tanh_fast(float x) {
    float y;
    asm("tanh.approx.f32 %0, %1;" : "=f"(y) : "f"(x));
    return y;
}
__device__ __forceinline__ float4 ldg_vol_v4(const float4* p) {
    float4 v;
    asm volatile("ld.volatile.global.v4.f32 {%0,%1,%2,%3}, [%4];"
                 : "=f"(v.x), "=f"(v.y), "=f"(v.z), "=f"(v.w) : "l"(p));
    return v;
}
__device__ __forceinline__ void stg_vol_v4(float4* p, float4 v) {
    asm volatile("st.volatile.global.v4.f32 [%0], {%1,%2,%3,%4};"
                 :: "l"(p), "f"(v.x), "f"(v.y), "f"(v.z), "f"(v.w) : "memory");
}
__device__ __forceinline__ int ld_acquire_i(const int* p) {
    int v;
    asm volatile("ld.acquire.gpu.global.s32 %0, [%1];" : "=r"(v) : "l"(p) : "memory");
    return v;
}
// packed fp32x2 ops
__device__ __forceinline__ void ffma2(unsigned long long& d,
                                      unsigned long long a, unsigned long long b) {
    asm("fma.rn.f32x2 %0, %1, %2, %0;" : "+l"(d) : "l"(a), "l"(b));
}
__device__ __forceinline__ unsigned long long add2(unsigned long long a,
                                                   unsigned long long b) {
    unsigned long long s;
    asm("add.rn.f32x2 %0, %1, %2;" : "=l"(s) : "l"(a), "l"(b));
    return s;
}
__device__ __forceinline__ float f32x2_hsum(unsigned long long a, unsigned long long b) {
    unsigned long long s = add2(a, b);
    float2 f = *reinterpret_cast<float2*>(&s);
    return f.x + f.y;
}

// ---------------- init: poison history, counters, seed h0 ---------------------
__global__ void poison_kernel() {
    const float4 s = make_float4(SENT, SENT, SENT, SENT);
    float4* p = (float4*)g_hist;
    const int total = (SEQ + 1) * (DIMS / 4);
    for (int w = blockIdx.x * blockDim.x + threadIdx.x; w < total;
         w += gridDim.x * blockDim.x)
        p[w] = s;
    int i = blockIdx.x * blockDim.x + threadIdx.x;
    if (i < NBLK) g_blkcnt[i] = 0;
    if (i == NBLK) g_Aprog = 0;
}
__global__ void seed_kernel(const float* __restrict__ h0) {
    int i = blockIdx.x * blockDim.x + threadIdx.x;
    if (i < DIMS) g_hist[i] = h0[i];
}

// ---------------- fused kernel: 128 scan CTAs + 16 producer CTAs ---------------
__global__ __launch_bounds__(THREADS, 1) void rnn_kernel(
    const float* __restrict__ X, const float* __restrict__ Whh,
    const float* __restrict__ Whi, const float* __restrict__ b,
    float* __restrict__ out)
{
    __shared__ __align__(16) float4 h_s[DIMS / 4];  // 8 KB (scan)
    __shared__ __align__(16) float  c_s[RPC];       // scan collect
    __shared__ __align__(16) float  Xs[TBLK][32];   // 4 KB (producer k-tile)

    const int tid = threadIdx.x;
    const int cta = blockIdx.x;

    if (cta < NCTA_SCAN) {
        // ================= SCAN: byte-identical champion (R5) =================
        const int wid  = tid >> 5;
        const int lane = tid & 31;
        const int row0 = cta * RPC + wid * 2;
        const int row1 = row0 + 1;

        ulonglong2 w0[16], w1[16];
        {
            const ulonglong2* W0 = (const ulonglong2*)(Whh + (size_t)row0 * DIMS);
            const ulonglong2* W1 = (const ulonglong2*)(Whh + (size_t)row1 * DIMS);
#pragma unroll
            for (int k = 0; k < 16; k++) {
                w0[k] = W0[lane + 32 * k];
                w1[k] = W1[lane + 32 * k];
            }
        }

        for (int t = 0; t < SEQ; t++) {
            const float4* hb = (const float4*)(g_hist + (size_t)t * DIMS);
            float4*       hn = (float4*)(g_hist + (size_t)(t + 1) * DIMS);

            // Step-constant operands, off the h critical chain. Once per
            // 32-step block, lane0 acquire-polls producer progress first.
            float a0 = 0.f, a1 = 0.f, xr0 = 0.f, xr1 = 0.f;
            if (lane == 0) {
                if ((t & (TBLK - 1)) == 0) {
                    while (ld_acquire_i(&g_Aprog) <= (t >> 5)) { }
                }
                a0  = g_A[(size_t)t * DIMS + row0];
                a1  = g_A[(size_t)t * DIMS + row1];
                xr0 = X[(size_t)t * DIMS + row0];
                xr1 = X[(size_t)t * DIMS + row1];
            }

            // Ingest h_prev — CHAMPION CODE, DO NOT TOUCH.
            {
                float4 va = ldg_vol_v4(hb + tid);
                float4 vb = ldg_vol_v4(hb + tid + THREADS);
                while (va.x == SENT || va.y == SENT || va.z == SENT || va.w == SENT)
                    va = ldg_vol_v4(hb + tid);
                while (vb.x == SENT || vb.y == SENT || vb.z == SENT || vb.w == SENT)
                    vb = ldg_vol_v4(hb + tid + THREADS);
                h_s[tid]           = va;
                h_s[tid + THREADS] = vb;
            }
            __syncthreads();   // bar A: h_s fully staged

            unsigned long long a0x = 0ull, a0y = 0ull, a1x = 0ull, a1y = 0ull;
#pragma unroll
            for (int k = 0; k < 16; k++) {
                ulonglong2 hv = *(const ulonglong2*)&h_s[lane + 32 * k];
                ffma2(a0x, w0[k].x, hv.x);  ffma2(a0y, w0[k].y, hv.y);
                ffma2(a1x, w1[k].x, hv.x);  ffma2(a1y, w1[k].y, hv.y);
            }
            float acc0 = f32x2_hsum(a0x, a0y);
            float acc1 = f32x2_hsum(a1x, a1y);
#pragma unroll
            for (int o = 16; o > 0; o >>= 1) {
                acc0 += __shfl_xor_sync(0xffffffffu, acc0, o);
                acc1 += __shfl_xor_sync(0xffffffffu, acc1, o);
            }

            if (lane == 0) {
                float h0n = tanh_fast(a0 + acc0);
                float h1n = tanh_fast(a1 + acc1);
                c_s[wid * 2 + 0] = h0n;
                c_s[wid * 2 + 1] = h1n;
                out[(size_t)t * DIMS + row0] = xr0 + h0n;
                out[(size_t)t * DIMS + row1] = xr1 + h1n;
            }
            __syncthreads();   // bar B

            if (tid < 4) stg_vol_v4(hn + cta * 4 + tid, *(const float4*)&c_s[tid * 4]);
        }
    } else {
        // ================= PRODUCER: A = X @ Whi^T + b =================
        // CTA g owns cols [128g, 128g+128); sweeps 32-step blocks in order.
        const int g  = cta - NCTA_SCAN;
        const int n  = g * 128 + (tid & 127);   // this thread's output column
        const int rh = tid >> 7;                // row half: rows rh*16..rh*16+15
        const float bb = b[n];
        const float* Wr = Whi + (size_t)n * DIMS;

        for (int blk = 0; blk < NBLK; blk++) {
            const int t0 = blk * TBLK;
            unsigned long long acc[16];
#pragma unroll
            for (int r = 0; r < 16; r++) acc[r] = 0ull;

            for (int kt = 0; kt < DIMS / 32; kt++) {    // 64 k-tiles of 32
                __syncthreads();                        // Xs reuse guard
                {   // coop stage X k-tile: 32 rows x 32 k
                    const int r = tid >> 3, c4 = (tid & 7) * 4;
                    *(float4*)&Xs[r][c4] =
                        *(const float4*)(X + (size_t)(t0 + r) * DIMS + kt * 32 + c4);
                }
                __syncthreads();

                ulonglong2 wv[8];                       // 32 k of W row n
#pragma unroll
                for (int i = 0; i < 8; i++)
                    wv[i] = *(const ulonglong2*)(Wr + kt * 32 + i * 4);
#pragma unroll
                for (int i = 0; i < 8; i++) {
#pragma unroll
                    for (int r = 0; r < 16; r++) {
                        ulonglong2 xv =
                            *(const ulonglong2*)&Xs[rh * 16 + r][i * 4];
                        ffma2(acc[r], wv[i].x, xv.x);
                        ffma2(acc[r], wv[i].y, xv.y);
                    }
                }
            }

            // write block slice + bias
#pragma unroll
            for (int r = 0; r < 16; r++) {
                float2 f = *reinterpret_cast<float2*>(&acc[r]);
                g_A[(size_t)(t0 + rh * 16 + r) * DIMS + n] = f.x + f.y + bb;
            }

            // publish progress: fence -> bar -> leader arrival; 16th arriver
            // advances the monotone prefix counter.
            __threadfence();
            __syncthreads();
            if (tid == 0) {
                int old = atomicAdd(&g_blkcnt[blk], 1);
                if (old == NCTA_GEMM - 1) {
                    __threadfence();
                    atomicMax(&g_Aprog, blk + 1);
                }
            }
        }
    }
}

// ---------------- launch -------------------------------------------------------
extern "C" void kernel_launch(void* const* d_in, const int* in_sizes, int n_in,
                              void* d_out, int out_size) {
    const float* X    = (const float*)d_in[0];  // [SEQ, DIMS]
    const float* W_hi = (const float*)d_in[1];  // [DIMS, DIMS]
    const float* W_hh = (const float*)d_in[2];  // [DIMS, DIMS]
    const float* b    = (const float*)d_in[3];  // [DIMS]
    const float* h0   = (const float*)d_in[4];  // [DIMS]
    float* out = (float*)d_out;

    poison_kernel<<<1024, 256>>>();
    seed_kernel<<<(DIMS + 255) / 256, 256>>>(h0);

    rnn_kernel<<<NCTA_ALL, THREADS>>>(X, W_hh, W_hi, b, out);
}

// round 16
// speedup vs baseline: 2.6577x; 2.6577x over previous
#include <cuda_runtime.h>
#include <cuda_bf16.h>
#include <mma.h>
#include <cstdint>

using namespace nvcuda;

#define DIMS 2048
#define SEQ  4096
#define SENT 2.0f   // sentinel: tanh output is in (-1,1), h0 = 0 -> never 2.0

// ---------------- scratch (static device globals; no allocation) ------------
__device__ float g_A[SEQ * DIMS];                         // A = X @ W_hi^T + b
__device__ __align__(16) float g_hist[(SEQ + 1) * DIMS];  // write-once h history
__device__ __align__(16) __nv_bfloat16 g_xhi[SEQ * DIMS];   // X split hi
__device__ __align__(16) __nv_bfloat16 g_xlo[SEQ * DIMS];   // X split lo
__device__ __align__(16) __nv_bfloat16 g_whi[DIMS * DIMS];  // W_hi split hi
__device__ __align__(16) __nv_bfloat16 g_wlo[DIMS * DIMS];  // W_hi split lo

// ---------------- small asm helpers -----------------------------------------
__device__ __forceinline__ float tanh_fast(float x) {
    float y;
    asm("tanh.approx.f32 %0, %1;" : "=f"(y) : "f"(x));
    return y;
}
__device__ __forceinline__ float4 ldg_vol_v4(const float4* p) {
    float4 v;
    asm volatile("ld.volatile.global.v4.f32 {%0,%1,%2,%3}, [%4];"
                 : "=f"(v.x), "=f"(v.y), "=f"(v.z), "=f"(v.w) : "l"(p));
    return v;
}
__device__ __forceinline__ void stg_vol_v4(float4* p, float4 v) {
    asm volatile("st.volatile.global.v4.f32 [%0], {%1,%2,%3,%4};"
                 :: "l"(p), "f"(v.x), "f"(v.y), "f"(v.z), "f"(v.w) : "memory");
}
__device__ __forceinline__ void ffma2(unsigned long long& d,
                                      unsigned long long a, unsigned long long b) {
    asm("fma.rn.f32x2 %0, %1, %2, %0;" : "+l"(d) : "l"(a), "l"(b));
}
__device__ __forceinline__ unsigned long long add2(unsigned long long a,
                                                   unsigned long long b) {
    unsigned long long s;
    asm("add.rn.f32x2 %0, %1, %2;" : "=l"(s) : "l"(a), "l"(b));
    return s;
}
__device__ __forceinline__ float f32x2_hsum(unsigned long long a, unsigned long long b) {
    unsigned long long s = add2(a, b);
    float2 f = *reinterpret_cast<float2*>(&s);
    return f.x + f.y;
}

// ---------------- init: poison history, seed h0 -------------------------------
__global__ void poison_kernel() {
    const float4 s = make_float4(SENT, SENT, SENT, SENT);
    float4* p = (float4*)g_hist;
    const int total = (SEQ + 1) * (DIMS / 4);
    for (int w = blockIdx.x * blockDim.x + threadIdx.x; w < total;
         w += gridDim.x * blockDim.x)
        p[w] = s;
}
__global__ void seed_kernel(const float* __restrict__ h0) {
    int i = blockIdx.x * blockDim.x + threadIdx.x;
    if (i < DIMS) g_hist[i] = h0[i];
}
// split fp32 -> bf16 hi + bf16 lo (residual)
__global__ void convert_kernel(const float* __restrict__ X,
                               const float* __restrict__ Whi) {
    const int NX = SEQ * DIMS, NW = DIMS * DIMS;
    for (int i = blockIdx.x * blockDim.x + threadIdx.x; i < NX + NW;
         i += gridDim.x * blockDim.x) {
        if (i < NX) {
            float x = X[i];
            __nv_bfloat16 h = __float2bfloat16(x);
            g_xhi[i] = h;
            g_xlo[i] = __float2bfloat16(x - __bfloat162float(h));
        } else {
            int j = i - NX;
            float x = Whi[j];
            __nv_bfloat16 h = __float2bfloat16(x);
            g_whi[j] = h;
            g_wlo[j] = __float2bfloat16(x - __bfloat162float(h));
        }
    }
}

// ---------------- phase 1: wmma split-bf16 GEMM --------------------------------
// A[m0:+128, n0:+128] = X @ Whi^T + b as Xhi*Whi + Xhi*Wlo + Xlo*Whi in fp32
// accumulators. 8 warps, warp tile 64x32 (4x2 m16n16k16 frags), BK=32 staging.
#define GEMM_T 256
#define PAD_LD 40                         // smem row stride (bf16 elems)
#define SOFF_XHI 0
#define SOFF_XLO (128 * PAD_LD)
#define SOFF_WHI (2 * 128 * PAD_LD)
#define SOFF_WLO (3 * 128 * PAD_LD)
#define SOFF_BIAS (4 * 128 * PAD_LD * 2)  // byte offset of bias_rep
#define TG_SMEM (SOFF_BIAS + 16 * 128 * 4)   // 40960 + 8192 = 49152 B

__global__ __launch_bounds__(GEMM_T, 1) void tgemm_kernel(const float* __restrict__ bias_g)
{
    extern __shared__ __align__(16) char sm[];
    __nv_bfloat16* bsm = (__nv_bfloat16*)sm;
    float* bias_rep = (float*)(sm + SOFF_BIAS);

    const int tid = threadIdx.x;
    const int wid = tid >> 5;
    const int wm  = wid & 1;        // 0..1: 64-row half
    const int wn  = wid >> 1;       // 0..3: 32-col strip
    const int m0  = blockIdx.y * 128;
    const int n0  = blockIdx.x * 128;

    // replicated-row bias tile: row r, col c -> bias[n0 + c]
    for (int i = tid; i < 16 * 128; i += GEMM_T)
        bias_rep[i] = bias_g[n0 + (i & 127)];
    __syncthreads();

    // accumulators initialized from bias (folds +b into the MMA for free)
    wmma::fragment<wmma::accumulator, 16, 16, 16, float> acc[4][2];
#pragma unroll
    for (int mi = 0; mi < 4; mi++)
#pragma unroll
        for (int nj = 0; nj < 2; nj++)
            wmma::load_matrix_sync(acc[mi][nj],
                                   bias_rep + wn * 32 + nj * 16, 128,
                                   wmma::mem_row_major);

    const int srow = tid >> 1;              // 0..127: staging row
    const int scol = (tid & 1) * 16;        // 0 or 16

    for (int it = 0; it < DIMS / 32; it++) {
        const int k0 = it * 32;
        __syncthreads();   // previous iter's fragment reads done
        {
            const size_t gx = (size_t)(m0 + srow) * DIMS + k0 + scol;
            const size_t gw = (size_t)(n0 + srow) * DIMS + k0 + scol;
            const int so = srow * PAD_LD + scol;
            *(uint4*)&bsm[SOFF_XHI + so]     = *(const uint4*)&g_xhi[gx];
            *(uint4*)&bsm[SOFF_XHI + so + 8] = *(const uint4*)&g_xhi[gx + 8];
            *(uint4*)&bsm[SOFF_XLO + so]     = *(const uint4*)&g_xlo[gx];
            *(uint4*)&bsm[SOFF_XLO + so + 8] = *(const uint4*)&g_xlo[gx + 8];
            *(uint4*)&bsm[SOFF_WHI + so]     = *(const uint4*)&g_whi[gw];
            *(uint4*)&bsm[SOFF_WHI + so + 8] = *(const uint4*)&g_whi[gw + 8];
            *(uint4*)&bsm[SOFF_WLO + so]     = *(const uint4*)&g_wlo[gw];
            *(uint4*)&bsm[SOFF_WLO + so + 8] = *(const uint4*)&g_wlo[gw + 8];
        }
        __syncthreads();

#pragma unroll
        for (int ks = 0; ks < 32; ks += 16) {
            wmma::fragment<wmma::matrix_a, 16, 16, 16, __nv_bfloat16,
                           wmma::row_major> ah[4], al[4];
            wmma::fragment<wmma::matrix_b, 16, 16, 16, __nv_bfloat16,
                           wmma::col_major> bh[2], bl[2];
#pragma unroll
            for (int mi = 0; mi < 4; mi++) {
                const int r = (wm * 64 + mi * 16) * PAD_LD + ks;
                wmma::load_matrix_sync(ah[mi], bsm + SOFF_XHI + r, PAD_LD);
                wmma::load_matrix_sync(al[mi], bsm + SOFF_XLO + r, PAD_LD);
            }
#pragma unroll
            for (int nj = 0; nj < 2; nj++) {
                const int r = (wn * 32 + nj * 16) * PAD_LD + ks;
                wmma::load_matrix_sync(bh[nj], bsm + SOFF_WHI + r, PAD_LD);
                wmma::load_matrix_sync(bl[nj], bsm + SOFF_WLO + r, PAD_LD);
            }
#pragma unroll
            for (int mi = 0; mi < 4; mi++)
#pragma unroll
                for (int nj = 0; nj < 2; nj++) {
                    wmma::mma_sync(acc[mi][nj], ah[mi], bh[nj], acc[mi][nj]);
                    wmma::mma_sync(acc[mi][nj], ah[mi], bl[nj], acc[mi][nj]);
                    wmma::mma_sync(acc[mi][nj], al[mi], bh[nj], acc[mi][nj]);
                }
        }
    }

#pragma unroll
    for (int mi = 0; mi < 4; mi++)
#pragma unroll
        for (int nj = 0; nj < 2; nj++)
            wmma::store_matrix_sync(
                g_A + (size_t)(m0 + wm * 64 + mi * 16) * DIMS
                    + n0 + wn * 32 + nj * 16,
                acc[mi][nj], DIMS, wmma::mem_row_major);
}

// ---------------- phase 2: persistent sequential RNN --------------------------
// EXACT champion (R5): value-signaled write-once history, sentinel poison,
// hot-spin payload polling, two bars per step, smem collect + tid<4 publish.
#define NCTA 128
#define RPC  16
#define RNN_THREADS 256

__global__ __launch_bounds__(RNN_THREADS, 1) void rnn_kernel(
    const float* __restrict__ X, const float* __restrict__ Whh,
    float* __restrict__ out)
{
    __shared__ __align__(16) float4 h_s[DIMS / 4];  // 8 KB
    __shared__ __align__(16) float  c_s[RPC];       // this CTA's 16 new h

    const int tid  = threadIdx.x;
    const int wid  = tid >> 5;
    const int lane = tid & 31;
    const int cta  = blockIdx.x;
    const int row0 = cta * RPC + wid * 2;
    const int row1 = row0 + 1;

    ulonglong2 w0[16], w1[16];
    {
        const ulonglong2* W0 = (const ulonglong2*)(Whh + (size_t)row0 * DIMS);
        const ulonglong2* W1 = (const ulonglong2*)(Whh + (size_t)row1 * DIMS);
#pragma unroll
        for (int k = 0; k < 16; k++) {
            w0[k] = W0[lane + 32 * k];
            w1[k] = W1[lane + 32 * k];
        }
    }

    for (int t = 0; t < SEQ; t++) {
        const float4* hb = (const float4*)(g_hist + (size_t)t * DIMS);
        float4*       hn = (float4*)(g_hist + (size_t)(t + 1) * DIMS);

        float a0 = 0.f, a1 = 0.f, xr0 = 0.f, xr1 = 0.f;
        if (lane == 0) {
            a0  = g_A[(size_t)t * DIMS + row0];
            a1  = g_A[(size_t)t * DIMS + row1];
            xr0 = X[(size_t)t * DIMS + row0];
            xr1 = X[(size_t)t * DIMS + row1];
        }

        {
            float4 va = ldg_vol_v4(hb + tid);
            float4 vb = ldg_vol_v4(hb + tid + RNN_THREADS);
            while (va.x == SENT || va.y == SENT || va.z == SENT || va.w == SENT)
                va = ldg_vol_v4(hb + tid);
            while (vb.x == SENT || vb.y == SENT || vb.z == SENT || vb.w == SENT)
                vb = ldg_vol_v4(hb + tid + RNN_THREADS);
            h_s[tid]               = va;
            h_s[tid + RNN_THREADS] = vb;
        }
        __syncthreads();   // bar A

        unsigned long long a0x = 0ull, a0y = 0ull, a1x = 0ull, a1y = 0ull;
#pragma unroll
        for (int k = 0; k < 16; k++) {
            ulonglong2 hv = *(const ulonglong2*)&h_s[lane + 32 * k];
            ffma2(a0x, w0[k].x, hv.x);  ffma2(a0y, w0[k].y, hv.y);
            ffma2(a1x, w1[k].x, hv.x);  ffma2(a1y, w1[k].y, hv.y);
        }
        float acc0 = f32x2_hsum(a0x, a0y);
        float acc1 = f32x2_hsum(a1x, a1y);
#pragma unroll
        for (int o = 16; o > 0; o >>= 1) {
            acc0 += __shfl_xor_sync(0xffffffffu, acc0, o);
            acc1 += __shfl_xor_sync(0xffffffffu, acc1, o);
        }

        if (lane == 0) {
            float h0n = tanh_fast(a0 + acc0);
            float h1n = tanh_fast(a1 + acc1);
            c_s[wid * 2 + 0] = h0n;
            c_s[wid * 2 + 1] = h1n;
            out[(size_t)t * DIMS + row0] = xr0 + h0n;
            out[(size_t)t * DIMS + row1] = xr1 + h1n;
        }
        __syncthreads();   // bar B

        if (tid < 4) stg_vol_v4(hn + cta * 4 + tid, *(const float4*)&c_s[tid * 4]);
    }
}

// ---------------- launch -------------------------------------------------------
extern "C" void kernel_launch(void* const* d_in, const int* in_sizes, int n_in,
                              void* d_out, int out_size) {
    const float* X    = (const float*)d_in[0];  // [SEQ, DIMS]
    const float* W_hi = (const float*)d_in[1];  // [DIMS, DIMS]
    const float* W_hh = (const float*)d_in[2];  // [DIMS, DIMS]
    const float* b    = (const float*)d_in[3];  // [DIMS]
    const float* h0   = (const float*)d_in[4];  // [DIMS]
    float* out = (float*)d_out;

    poison_kernel<<<1024, 256>>>();
    seed_kernel<<<(DIMS + 255) / 256, 256>>>(h0);
    convert_kernel<<<1024, 256>>>(X, W_hi);

    cudaFuncSetAttribute(tgemm_kernel,
                         cudaFuncAttributeMaxDynamicSharedMemorySize, TG_SMEM);
    dim3 tg(DIMS / 128, SEQ / 128);             // (16, 32)
    tgemm_kernel<<<tg, GEMM_T, TG_SMEM>>>(b);

    rnn_kernel<<<NCTA, RNN_THREADS>>>(X, W_hh, out);
}